// round 1
// baseline (speedup 1.0000x reference)
#include <cuda_runtime.h>

#define DEV_INLINE __device__ __forceinline__

namespace {
constexpr int Bb = 8, N_ = 196, D_ = 128, DFF_ = 256, C_ = 1000;
constexpr int M_ = Bb * N_;            // 1568 total rows
constexpr float NEG = -1e30f;
}

// persistent scratch (allocation-free rule: __device__ globals)
__device__ float g_h[M_ * D_];         // x (residual stream)
__device__ float g_xn[M_ * D_];        // pnorm(x)
__device__ float g_q[M_ * D_];
__device__ float g_k[M_ * D_];
__device__ float g_vt[Bb * D_ * N_];   // v transposed per batch: [b][d][n]
__device__ float g_sc[Bb * N_ * N_];   // attention scores
__device__ float g_ff[M_ * DFF_];      // ff hidden
__device__ float g_pool[Bb * D_];

DEV_INLINE float warpMax(float v) {
#pragma unroll
    for (int m = 16; m > 0; m >>= 1)
        v = fmaxf(v, __shfl_xor_sync(0xffffffffu, v, m));
    return v;
}

// ============================================================
// Config A GEMM: out[m,n] = max_k(A[m,k] + W[n,k]), K=128
// BM=32, BN=64, BK=32, 256 threads, per-thread 2x4
// MODE 0: qkv fused (A=g_xn, N=384 -> q|k|vt)
// MODE 1: scores per batch (A=q[b], W=k[b], M=N=196, guards)
// MODE 2: ff1 (A=g_xn, W=ff1_W 256x128, tau fused)
// ============================================================
template <int MODE>
__global__ void __launch_bounds__(256) gemmA_kernel(
    const float* __restrict__ W0, const float* __restrict__ W1,
    const float* __restrict__ W2, const float* __restrict__ tau) {
    __shared__ __align__(16) float As[32][34];
    __shared__ __align__(16) float Ws[32][68];
    const int tid = threadIdx.x;
    const int m0 = blockIdx.x * 32;
    const int n0 = blockIdx.y * 64;

    const float* Ap;
    const float* Wp;
    if (MODE == 0) {
        Ap = g_xn;
        int sec = n0 >> 7;
        Wp = (sec == 0 ? W0 : (sec == 1 ? W1 : W2)) + (n0 & 127) * 128;
    } else if (MODE == 1) {
        int b = blockIdx.z;
        Ap = g_q + b * N_ * D_;
        Wp = g_k + b * N_ * D_;
    } else {
        Ap = g_xn;
        Wp = W0 + n0 * 128;
    }

    const int kq = tid & 7, l = tid >> 3;   // loader coords
    float acc[2][4];
#pragma unroll
    for (int r = 0; r < 2; r++)
#pragma unroll
        for (int c = 0; c < 4; c++) acc[r][c] = NEG;

    const int r0 = (tid >> 4) * 2, c0 = (tid & 15) * 4;

    for (int k0 = 0; k0 < 128; k0 += 32) {
        // A tile 32x32
        float4 av;
        if (MODE == 1 && (m0 + l) >= N_) av = make_float4(NEG, NEG, NEG, NEG);
        else av = *(const float4*)(Ap + (m0 + l) * 128 + k0 + kq * 4);
        As[kq * 4 + 0][l] = av.x; As[kq * 4 + 1][l] = av.y;
        As[kq * 4 + 2][l] = av.z; As[kq * 4 + 3][l] = av.w;
        // W tile 64x32
#pragma unroll
        for (int p = 0; p < 2; p++) {
            int nl = l + p * 32;
            float4 wv;
            if (MODE == 1 && (n0 + nl) >= N_) wv = make_float4(NEG, NEG, NEG, NEG);
            else {
                int wrow = (MODE == 1) ? (n0 + nl) : nl;
                wv = *(const float4*)(Wp + wrow * 128 + k0 + kq * 4);
            }
            Ws[kq * 4 + 0][nl] = wv.x; Ws[kq * 4 + 1][nl] = wv.y;
            Ws[kq * 4 + 2][nl] = wv.z; Ws[kq * 4 + 3][nl] = wv.w;
        }
        __syncthreads();
#pragma unroll
        for (int kk = 0; kk < 32; kk++) {
            float a0 = As[kk][r0], a1 = As[kk][r0 + 1];
            float4 w = *(const float4*)&Ws[kk][c0];
            acc[0][0] = fmaxf(acc[0][0], a0 + w.x);
            acc[0][1] = fmaxf(acc[0][1], a0 + w.y);
            acc[0][2] = fmaxf(acc[0][2], a0 + w.z);
            acc[0][3] = fmaxf(acc[0][3], a0 + w.w);
            acc[1][0] = fmaxf(acc[1][0], a1 + w.x);
            acc[1][1] = fmaxf(acc[1][1], a1 + w.y);
            acc[1][2] = fmaxf(acc[1][2], a1 + w.z);
            acc[1][3] = fmaxf(acc[1][3], a1 + w.w);
        }
        __syncthreads();
    }

    if (MODE == 0) {
#pragma unroll
        for (int r = 0; r < 2; r++) {
            int gm = m0 + r0 + r;
            int b = gm / 196, i = gm - b * 196;
#pragma unroll
            for (int c = 0; c < 4; c++) {
                int gn = n0 + c0 + c;
                float v = acc[r][c];
                if (gn < 128)       g_q[gm * 128 + gn] = v;
                else if (gn < 256)  g_k[gm * 128 + (gn - 128)] = v;
                else                g_vt[(b * 128 + (gn - 256)) * N_ + i] = v;
            }
        }
    } else if (MODE == 1) {
        int b = blockIdx.z;
        float* out = g_sc + b * N_ * N_;
#pragma unroll
        for (int r = 0; r < 2; r++) {
            int i = m0 + r0 + r;
            if (i < N_) {
#pragma unroll
                for (int c = 0; c < 4; c++) {
                    int j = n0 + c0 + c;
                    if (j < N_) out[i * N_ + j] = acc[r][c];
                }
            }
        }
    } else {
        float tv = tau[0];
#pragma unroll
        for (int r = 0; r < 2; r++) {
            int gm = m0 + r0 + r;
#pragma unroll
            for (int c = 0; c < 4; c++)
                g_ff[gm * 256 + n0 + c0 + c] = fmaxf(acc[r][c], tv);
        }
    }
}

// ============================================================
// Config B core: BM=16, BN=128 (full D), BK=32, 256 threads,
// per-thread 2 rows x 4 cols; each warp owns 2 full rows.
// ============================================================
template <bool DO_RM>
DEV_INLINE void innerB(const float (&As)[32][18], const float (&Ws)[32][132],
                       float (&acc)[2][4], float (&rm)[2], int r0, int c0) {
#pragma unroll
    for (int kk = 0; kk < 32; kk++) {
        float a0 = As[kk][r0], a1 = As[kk][r0 + 1];
        float4 w = *(const float4*)&Ws[kk][c0];
        if (DO_RM) { rm[0] = fmaxf(rm[0], a0); rm[1] = fmaxf(rm[1], a1); }
        acc[0][0] = fmaxf(acc[0][0], a0 + w.x);
        acc[0][1] = fmaxf(acc[0][1], a0 + w.y);
        acc[0][2] = fmaxf(acc[0][2], a0 + w.z);
        acc[0][3] = fmaxf(acc[0][3], a0 + w.w);
        acc[1][0] = fmaxf(acc[1][0], a1 + w.x);
        acc[1][1] = fmaxf(acc[1][1], a1 + w.y);
        acc[1][2] = fmaxf(acc[1][2], a1 + w.z);
        acc[1][3] = fmaxf(acc[1][3], a1 + w.w);
    }
}

// embed: patchify gather + trop_mm(embed_W) + pos, then pnorm; writes g_h, g_xn
__global__ void __launch_bounds__(256) embed_kernel(
    const float* __restrict__ x, const float* __restrict__ eW,
    const float* __restrict__ pos) {
    __shared__ __align__(16) float As[32][18];
    __shared__ __align__(16) float Ws[32][132];
    const int tid = threadIdx.x;
    const int m0 = blockIdx.x * 16;
    const int kq = tid & 7, l = tid >> 3;
    float acc[2][4];
    float rm[2];
#pragma unroll
    for (int r = 0; r < 2; r++)
#pragma unroll
        for (int c = 0; c < 4; c++) acc[r][c] = NEG;
    const int r0 = (tid >> 5) * 2, c0 = (tid & 31) * 4;

    for (int k0 = 0; k0 < 256; k0 += 32) {
        if (tid < 128) {
            int gm = m0 + l;                 // l in 0..15
            int b = gm / 196, n = gm - b * 196;
            int gy = n / 14, gx = n - gy * 14;
            int k = k0 + kq * 4;
            int py = k >> 4, px = k & 15;
            float4 av = *(const float4*)(x + b * 50176 + (gy * 16 + py) * 224 + gx * 16 + px);
            As[kq * 4 + 0][l] = av.x; As[kq * 4 + 1][l] = av.y;
            As[kq * 4 + 2][l] = av.z; As[kq * 4 + 3][l] = av.w;
        }
#pragma unroll
        for (int p = 0; p < 4; p++) {
            int nl = l + p * 32;
            float4 wv = *(const float4*)(eW + nl * 256 + k0 + kq * 4);
            Ws[kq * 4 + 0][nl] = wv.x; Ws[kq * 4 + 1][nl] = wv.y;
            Ws[kq * 4 + 2][nl] = wv.z; Ws[kq * 4 + 3][nl] = wv.w;
        }
        __syncthreads();
        innerB<false>(As, Ws, acc, rm, r0, c0);
        __syncthreads();
    }

#pragma unroll
    for (int r = 0; r < 2; r++) {
        int gm = m0 + r0 + r;
        int n = gm % 196;
        float h[4];
#pragma unroll
        for (int c = 0; c < 4; c++) h[c] = acc[r][c] + pos[n * 128 + c0 + c];
        float lm = fmaxf(fmaxf(h[0], h[1]), fmaxf(h[2], h[3]));
        float dm = warpMax(lm);
        int base = gm * 128 + c0;
#pragma unroll
        for (int c = 0; c < 4; c++) {
            g_h[base + c] = h[c];
            g_xn[base + c] = h[c] - dm;
        }
    }
}

// attention out: o[i,d] = max_j(sc[i,j] + vt[d,j]) - rowmax_j(sc[i,j]);
// then a = pnorm(o); x = max(x, a); xn = pnorm(x). K=196 (guarded).
__global__ void __launch_bounds__(256) attnout_kernel() {
    __shared__ __align__(16) float As[32][18];
    __shared__ __align__(16) float Ws[32][132];
    const int tid = threadIdx.x;
    const int b = blockIdx.y;
    const int m0 = blockIdx.x * 16;
    const float* Ap = g_sc + b * N_ * N_;
    const float* Wp = g_vt + b * D_ * N_;
    const int kq = tid & 7, l = tid >> 3;
    float acc[2][4];
    float rm[2] = {NEG, NEG};
#pragma unroll
    for (int r = 0; r < 2; r++)
#pragma unroll
        for (int c = 0; c < 4; c++) acc[r][c] = NEG;
    const int r0 = (tid >> 5) * 2, c0 = (tid & 31) * 4;

    for (int k0 = 0; k0 < 196; k0 += 32) {
        bool kvalid = (kq * 4) < (196 - k0);
        if (tid < 128) {
            int gm = m0 + l;
            float4 av = (gm < N_ && kvalid)
                            ? *(const float4*)(Ap + gm * 196 + k0 + kq * 4)
                            : make_float4(NEG, NEG, NEG, NEG);
            As[kq * 4 + 0][l] = av.x; As[kq * 4 + 1][l] = av.y;
            As[kq * 4 + 2][l] = av.z; As[kq * 4 + 3][l] = av.w;
        }
#pragma unroll
        for (int p = 0; p < 4; p++) {
            int nl = l + p * 32;
            float4 wv = kvalid ? *(const float4*)(Wp + nl * 196 + k0 + kq * 4)
                               : make_float4(NEG, NEG, NEG, NEG);
            Ws[kq * 4 + 0][nl] = wv.x; Ws[kq * 4 + 1][nl] = wv.y;
            Ws[kq * 4 + 2][nl] = wv.z; Ws[kq * 4 + 3][nl] = wv.w;
        }
        __syncthreads();
        innerB<true>(As, Ws, acc, rm, r0, c0);
        __syncthreads();
    }

#pragma unroll
    for (int r = 0; r < 2; r++) {
        int i = m0 + r0 + r;
        if (i < N_) {                       // uniform per warp
            float o[4];
#pragma unroll
            for (int c = 0; c < 4; c++) o[c] = acc[r][c] - rm[r];
            float dm = warpMax(fmaxf(fmaxf(o[0], o[1]), fmaxf(o[2], o[3])));
            int base = (b * 196 + i) * 128 + c0;
            float nx[4];
#pragma unroll
            for (int c = 0; c < 4; c++) {
                float a = o[c] - dm;
                nx[c] = fmaxf(g_h[base + c], a);
            }
            float dm2 = warpMax(fmaxf(fmaxf(nx[0], nx[1]), fmaxf(nx[2], nx[3])));
#pragma unroll
            for (int c = 0; c < 4; c++) {
                g_h[base + c] = nx[c];
                g_xn[base + c] = nx[c] - dm2;
            }
        }
    }
}

// ff2: out = trop_mm(g_ff, f2W) (K=256); ff = pnorm(out); x = max(x, ff); xn = pnorm(x)
__global__ void __launch_bounds__(256) ff2_kernel(const float* __restrict__ W) {
    __shared__ __align__(16) float As[32][18];
    __shared__ __align__(16) float Ws[32][132];
    const int tid = threadIdx.x;
    const int m0 = blockIdx.x * 16;
    const int kq = tid & 7, l = tid >> 3;
    float acc[2][4];
    float rm[2];
#pragma unroll
    for (int r = 0; r < 2; r++)
#pragma unroll
        for (int c = 0; c < 4; c++) acc[r][c] = NEG;
    const int r0 = (tid >> 5) * 2, c0 = (tid & 31) * 4;

    for (int k0 = 0; k0 < 256; k0 += 32) {
        if (tid < 128) {
            float4 av = *(const float4*)(g_ff + (m0 + l) * 256 + k0 + kq * 4);
            As[kq * 4 + 0][l] = av.x; As[kq * 4 + 1][l] = av.y;
            As[kq * 4 + 2][l] = av.z; As[kq * 4 + 3][l] = av.w;
        }
#pragma unroll
        for (int p = 0; p < 4; p++) {
            int nl = l + p * 32;
            float4 wv = *(const float4*)(W + nl * 256 + k0 + kq * 4);
            Ws[kq * 4 + 0][nl] = wv.x; Ws[kq * 4 + 1][nl] = wv.y;
            Ws[kq * 4 + 2][nl] = wv.z; Ws[kq * 4 + 3][nl] = wv.w;
        }
        __syncthreads();
        innerB<false>(As, Ws, acc, rm, r0, c0);
        __syncthreads();
    }

#pragma unroll
    for (int r = 0; r < 2; r++) {
        int gm = m0 + r0 + r;
        float dm = warpMax(fmaxf(fmaxf(acc[r][0], acc[r][1]), fmaxf(acc[r][2], acc[r][3])));
        int base = gm * 128 + c0;
        float nx[4];
#pragma unroll
        for (int c = 0; c < 4; c++)
            nx[c] = fmaxf(g_h[base + c], acc[r][c] - dm);
        float dm2 = warpMax(fmaxf(fmaxf(nx[0], nx[1]), fmaxf(nx[2], nx[3])));
#pragma unroll
        for (int c = 0; c < 4; c++) {
            g_h[base + c] = nx[c];
            g_xn[base + c] = nx[c] - dm2;
        }
    }
}

__global__ void pool_kernel() {
    int b = blockIdx.x, d = threadIdx.x;
    float m = NEG;
    for (int n = 0; n < N_; n++)
        m = fmaxf(m, g_h[(b * N_ + n) * D_ + d]);
    g_pool[b * D_ + d] = m;
}

__global__ void __launch_bounds__(256) head_kernel(
    const float* __restrict__ hW, const float* __restrict__ ls,
    float* __restrict__ out) {
    __shared__ float sp[128];
    const int b = blockIdx.y;
    const int tid = threadIdx.x;
    if (tid < 128) sp[tid] = g_pool[b * 128 + tid];
    __syncthreads();
    int c = blockIdx.x * 256 + tid;
    if (c < C_) {
        float acc = NEG;
#pragma unroll 8
        for (int d = 0; d < 128; d += 4) {
            float4 w = *(const float4*)(hW + c * 128 + d);
            acc = fmaxf(acc, sp[d + 0] + w.x);
            acc = fmaxf(acc, sp[d + 1] + w.y);
            acc = fmaxf(acc, sp[d + 2] + w.z);
            acc = fmaxf(acc, sp[d + 3] + w.w);
        }
        out[b * C_ + c] = acc * ls[0];
    }
}

extern "C" void kernel_launch(void* const* d_in, const int* in_sizes, int n_in,
                              void* d_out, int out_size) {
    const float* x   = (const float*)d_in[0];
    const float* eW  = (const float*)d_in[1];
    const float* pos = (const float*)d_in[2];
    const float* qW[2]  = {(const float*)d_in[3],  (const float*)d_in[9]};
    const float* kW[2]  = {(const float*)d_in[4],  (const float*)d_in[10]};
    const float* vW[2]  = {(const float*)d_in[5],  (const float*)d_in[11]};
    const float* f1[2]  = {(const float*)d_in[6],  (const float*)d_in[12]};
    const float* f2[2]  = {(const float*)d_in[7],  (const float*)d_in[13]};
    const float* tau[2] = {(const float*)d_in[8],  (const float*)d_in[14]};
    const float* hW = (const float*)d_in[15];
    const float* ls = (const float*)d_in[16];
    float* out = (float*)d_out;

    embed_kernel<<<98, 256>>>(x, eW, pos);                       // g_h, g_xn
    for (int l = 0; l < 2; l++) {
        gemmA_kernel<0><<<dim3(49, 6), 256>>>(qW[l], kW[l], vW[l], nullptr);   // q,k,vt
        gemmA_kernel<1><<<dim3(7, 4, 8), 256>>>(nullptr, nullptr, nullptr, nullptr); // scores
        attnout_kernel<<<dim3(13, 8), 256>>>();                  // fused attn-out + residual + pnorms
        gemmA_kernel<2><<<dim3(49, 4), 256>>>(f1[l], nullptr, nullptr, tau[l]); // ff1 + tau
        ff2_kernel<<<98, 256>>>(f2[l]);                          // ff2 + pnorm + residual + pnorm
    }
    pool_kernel<<<8, 128>>>();
    head_kernel<<<dim3(4, 8), 256>>>(hW, ls, out);
}

// round 2
// speedup vs baseline: 1.0634x; 1.0634x over previous
#include <cuda_runtime.h>

#define DEV_INLINE __device__ __forceinline__

namespace {
constexpr int Bb = 8, N_ = 196, D_ = 128, DFF_ = 256, C_ = 1000;
constexpr int M_ = Bb * N_;            // 1568 total rows
constexpr float NEG = -1e30f;
}

// persistent scratch (allocation-free rule: __device__ globals)
__device__ float g_h[M_ * D_];         // x (residual stream)
__device__ float g_xn[M_ * D_];        // pnorm(x)
__device__ float g_q[M_ * D_];
__device__ float g_k[M_ * D_];
__device__ float g_vt[Bb * D_ * N_];   // v transposed per batch: [b][d][n]
__device__ float g_sc[Bb * N_ * N_];   // attention scores
__device__ float g_ff[M_ * DFF_];      // ff hidden
__device__ float g_pool[Bb * D_];

DEV_INLINE float warpMax(float v) {
#pragma unroll
    for (int m = 16; m > 0; m >>= 1)
        v = fmaxf(v, __shfl_xor_sync(0xffffffffu, v, m));
    return v;
}

// ============================================================
// Config A GEMM: out[m,n] = max_k(A[m,k] + W[n,k]), K=128
// BM=32, BN=64, BK=32, 256 threads, per-thread 2x4
// MODE 0: qkv fused (A=g_xn, N=384 -> q|k|vt)
// MODE 1: scores per batch (A=q[b], W=k[b], M=N=196, guards)
// MODE 2: ff1 (A=g_xn, W=ff1_W 256x128, tau fused)
// ============================================================
template <int MODE>
__global__ void __launch_bounds__(256) gemmA_kernel(
    const float* __restrict__ W0, const float* __restrict__ W1,
    const float* __restrict__ W2, const float* __restrict__ tau) {
    __shared__ __align__(16) float As[32][34];
    __shared__ __align__(16) float Ws[32][68];
    const int tid = threadIdx.x;
    const int m0 = blockIdx.x * 32;
    const int n0 = blockIdx.y * 64;

    const float* Ap;
    const float* Wp;
    if (MODE == 0) {
        Ap = g_xn;
        int sec = n0 >> 7;
        Wp = (sec == 0 ? W0 : (sec == 1 ? W1 : W2)) + (n0 & 127) * 128;
    } else if (MODE == 1) {
        int b = blockIdx.z;
        Ap = g_q + b * N_ * D_;
        Wp = g_k + b * N_ * D_;
    } else {
        Ap = g_xn;
        Wp = W0 + n0 * 128;
    }

    const int kq = tid & 7, l = tid >> 3;   // loader coords
    float acc[2][4];
#pragma unroll
    for (int r = 0; r < 2; r++)
#pragma unroll
        for (int c = 0; c < 4; c++) acc[r][c] = NEG;

    const int r0 = (tid >> 4) * 2, c0 = (tid & 15) * 4;

    for (int k0 = 0; k0 < 128; k0 += 32) {
        // A tile 32x32
        float4 av;
        if (MODE == 1 && (m0 + l) >= N_) av = make_float4(NEG, NEG, NEG, NEG);
        else av = *(const float4*)(Ap + (m0 + l) * 128 + k0 + kq * 4);
        As[kq * 4 + 0][l] = av.x; As[kq * 4 + 1][l] = av.y;
        As[kq * 4 + 2][l] = av.z; As[kq * 4 + 3][l] = av.w;
        // W tile 64x32
#pragma unroll
        for (int p = 0; p < 2; p++) {
            int nl = l + p * 32;
            float4 wv;
            if (MODE == 1 && (n0 + nl) >= N_) wv = make_float4(NEG, NEG, NEG, NEG);
            else {
                int wrow = (MODE == 1) ? (n0 + nl) : nl;
                wv = *(const float4*)(Wp + wrow * 128 + k0 + kq * 4);
            }
            Ws[kq * 4 + 0][nl] = wv.x; Ws[kq * 4 + 1][nl] = wv.y;
            Ws[kq * 4 + 2][nl] = wv.z; Ws[kq * 4 + 3][nl] = wv.w;
        }
        __syncthreads();
#pragma unroll
        for (int kk = 0; kk < 32; kk++) {
            float a0 = As[kk][r0], a1 = As[kk][r0 + 1];
            float4 w = *(const float4*)&Ws[kk][c0];
            acc[0][0] = fmaxf(acc[0][0], a0 + w.x);
            acc[0][1] = fmaxf(acc[0][1], a0 + w.y);
            acc[0][2] = fmaxf(acc[0][2], a0 + w.z);
            acc[0][3] = fmaxf(acc[0][3], a0 + w.w);
            acc[1][0] = fmaxf(acc[1][0], a1 + w.x);
            acc[1][1] = fmaxf(acc[1][1], a1 + w.y);
            acc[1][2] = fmaxf(acc[1][2], a1 + w.z);
            acc[1][3] = fmaxf(acc[1][3], a1 + w.w);
        }
        __syncthreads();
    }

    if (MODE == 0) {
#pragma unroll
        for (int r = 0; r < 2; r++) {
            int gm = m0 + r0 + r;
            int b = gm / 196, i = gm - b * 196;
#pragma unroll
            for (int c = 0; c < 4; c++) {
                int gn = n0 + c0 + c;
                float v = acc[r][c];
                if (gn < 128)       g_q[gm * 128 + gn] = v;
                else if (gn < 256)  g_k[gm * 128 + (gn - 128)] = v;
                else                g_vt[(b * 128 + (gn - 256)) * N_ + i] = v;
            }
        }
    } else if (MODE == 1) {
        int b = blockIdx.z;
        float* out = g_sc + b * N_ * N_;
#pragma unroll
        for (int r = 0; r < 2; r++) {
            int i = m0 + r0 + r;
            if (i < N_) {
#pragma unroll
                for (int c = 0; c < 4; c++) {
                    int j = n0 + c0 + c;
                    if (j < N_) out[i * N_ + j] = acc[r][c];
                }
            }
        }
    } else {
        float tv = tau[0];
#pragma unroll
        for (int r = 0; r < 2; r++) {
            int gm = m0 + r0 + r;
#pragma unroll
            for (int c = 0; c < 4; c++)
                g_ff[gm * 256 + n0 + c0 + c] = fmaxf(acc[r][c], tv);
        }
    }
}

// ============================================================
// Config B (split-K, 512 threads): BM=16, BN=128 (full D), BK=32.
// Two 256-thread groups each cover half of K; partial maxes are
// combined through smem (max is idempotent: the unbalanced group's
// dummy tail tile just recomputes stale smem — harmless).
// Group 0 then runs the fused row-wise epilogue.
// ============================================================
template <bool DO_RM>
DEV_INLINE void innerB(const float (&As)[32][18], const float (&Ws)[32][132],
                       float (&acc)[2][4], float (&rm)[2], int r0, int c0) {
#pragma unroll
    for (int kk = 0; kk < 32; kk++) {
        float a0 = As[kk][r0], a1 = As[kk][r0 + 1];
        float4 w = *(const float4*)&Ws[kk][c0];
        if (DO_RM) { rm[0] = fmaxf(rm[0], a0); rm[1] = fmaxf(rm[1], a1); }
        acc[0][0] = fmaxf(acc[0][0], a0 + w.x);
        acc[0][1] = fmaxf(acc[0][1], a0 + w.y);
        acc[0][2] = fmaxf(acc[0][2], a0 + w.z);
        acc[0][3] = fmaxf(acc[0][3], a0 + w.w);
        acc[1][0] = fmaxf(acc[1][0], a1 + w.x);
        acc[1][1] = fmaxf(acc[1][1], a1 + w.y);
        acc[1][2] = fmaxf(acc[1][2], a1 + w.z);
        acc[1][3] = fmaxf(acc[1][3], a1 + w.w);
    }
}

// embed: patchify gather + trop_mm(embed_W) + pos, then pnorm; writes g_h, g_xn
__global__ void __launch_bounds__(512) embed_kernel(
    const float* __restrict__ x, const float* __restrict__ eW,
    const float* __restrict__ pos) {
    __shared__ __align__(16) float As[2][32][18];
    __shared__ __align__(16) float Ws[2][32][132];
    __shared__ float red[16][132];
    const int tid = threadIdx.x;
    const int wg = tid >> 8;
    const int wtid = tid & 255;
    const int m0 = blockIdx.x * 16;
    const int kq = wtid & 7, l = wtid >> 3;
    float acc[2][4];
    float rm[2];
#pragma unroll
    for (int r = 0; r < 2; r++)
#pragma unroll
        for (int c = 0; c < 4; c++) acc[r][c] = NEG;
    const int r0 = (wtid >> 5) * 2, c0 = (wtid & 31) * 4;
    const int kbase = wg * 128;

#pragma unroll
    for (int t = 0; t < 4; t++) {
        int k0 = kbase + t * 32;
        if (wtid < 128) {
            int gm = m0 + l;                 // l in 0..15
            int b = gm / 196, n = gm - b * 196;
            int gy = n / 14, gx = n - gy * 14;
            int k = k0 + kq * 4;
            int py = k >> 4, px = k & 15;
            float4 av = *(const float4*)(x + b * 50176 + (gy * 16 + py) * 224 + gx * 16 + px);
            As[wg][kq * 4 + 0][l] = av.x; As[wg][kq * 4 + 1][l] = av.y;
            As[wg][kq * 4 + 2][l] = av.z; As[wg][kq * 4 + 3][l] = av.w;
        }
#pragma unroll
        for (int p = 0; p < 4; p++) {
            int nl = l + p * 32;
            float4 wv = *(const float4*)(eW + nl * 256 + k0 + kq * 4);
            Ws[wg][kq * 4 + 0][nl] = wv.x; Ws[wg][kq * 4 + 1][nl] = wv.y;
            Ws[wg][kq * 4 + 2][nl] = wv.z; Ws[wg][kq * 4 + 3][nl] = wv.w;
        }
        __syncthreads();
        innerB<false>(As[wg], Ws[wg], acc, rm, r0, c0);
        __syncthreads();
    }

    if (wg == 1) {
#pragma unroll
        for (int r = 0; r < 2; r++)
#pragma unroll
            for (int c = 0; c < 4; c++) red[r0 + r][c0 + c] = acc[r][c];
    }
    __syncthreads();
    if (wg == 1) return;

#pragma unroll
    for (int r = 0; r < 2; r++) {
        int gm = m0 + r0 + r;
        int n = gm % 196;
        float h[4];
#pragma unroll
        for (int c = 0; c < 4; c++)
            h[c] = fmaxf(acc[r][c], red[r0 + r][c0 + c]) + pos[n * 128 + c0 + c];
        float lm = fmaxf(fmaxf(h[0], h[1]), fmaxf(h[2], h[3]));
        float dm = warpMax(lm);
        int base = gm * 128 + c0;
#pragma unroll
        for (int c = 0; c < 4; c++) {
            g_h[base + c] = h[c];
            g_xn[base + c] = h[c] - dm;
        }
    }
}

// attention out: o[i,d] = max_j(sc[i,j] + vt[d,j]) - rowmax_j(sc[i,j]);
// then a = pnorm(o); x = max(x, a); xn = pnorm(x). K=196, split 128+68.
__global__ void __launch_bounds__(512) attnout_kernel() {
    __shared__ __align__(16) float As[2][32][18];
    __shared__ __align__(16) float Ws[2][32][132];
    __shared__ float red[16][132];
    __shared__ float redrm[16];
    const int tid = threadIdx.x;
    const int wg = tid >> 8;
    const int wtid = tid & 255;
    const int b = blockIdx.y;
    const int m0 = blockIdx.x * 16;
    const float* Ap = g_sc + b * N_ * N_;
    const float* Wp = g_vt + b * D_ * N_;
    const int kq = wtid & 7, l = wtid >> 3;
    float acc[2][4];
    float rm[2] = {NEG, NEG};
#pragma unroll
    for (int r = 0; r < 2; r++)
#pragma unroll
        for (int c = 0; c < 4; c++) acc[r][c] = NEG;
    const int r0 = (wtid >> 5) * 2, c0 = (wtid & 31) * 4;
    const int kbase = wg * 128;

#pragma unroll
    for (int t = 0; t < 4; t++) {
        int k0 = kbase + t * 32;
        bool tvalid = k0 < 196;                    // wg1 t=3 is a dummy (recompute)
        bool kvalid = tvalid && (kq * 4 < 196 - k0);
        if (tvalid) {
            if (wtid < 128) {
                int gm = m0 + l;
                float4 av = (gm < N_ && kvalid)
                                ? *(const float4*)(Ap + gm * 196 + k0 + kq * 4)
                                : make_float4(NEG, NEG, NEG, NEG);
                As[wg][kq * 4 + 0][l] = av.x; As[wg][kq * 4 + 1][l] = av.y;
                As[wg][kq * 4 + 2][l] = av.z; As[wg][kq * 4 + 3][l] = av.w;
            }
#pragma unroll
            for (int p = 0; p < 4; p++) {
                int nl = l + p * 32;
                float4 wv = kvalid ? *(const float4*)(Wp + nl * 196 + k0 + kq * 4)
                                   : make_float4(NEG, NEG, NEG, NEG);
                Ws[wg][kq * 4 + 0][nl] = wv.x; Ws[wg][kq * 4 + 1][nl] = wv.y;
                Ws[wg][kq * 4 + 2][nl] = wv.z; Ws[wg][kq * 4 + 3][nl] = wv.w;
            }
        }
        __syncthreads();
        innerB<true>(As[wg], Ws[wg], acc, rm, r0, c0);
        __syncthreads();
    }

    if (wg == 1) {
#pragma unroll
        for (int r = 0; r < 2; r++) {
#pragma unroll
            for (int c = 0; c < 4; c++) red[r0 + r][c0 + c] = acc[r][c];
            if ((wtid & 31) == 0) redrm[r0 + r] = rm[r];
        }
    }
    __syncthreads();
    if (wg == 1) return;

#pragma unroll
    for (int r = 0; r < 2; r++) {
        int i = m0 + r0 + r;
        if (i < N_) {                       // uniform per warp
            float frm = fmaxf(rm[r], redrm[r0 + r]);
            float o[4];
#pragma unroll
            for (int c = 0; c < 4; c++)
                o[c] = fmaxf(acc[r][c], red[r0 + r][c0 + c]) - frm;
            float dm = warpMax(fmaxf(fmaxf(o[0], o[1]), fmaxf(o[2], o[3])));
            int base = (b * 196 + i) * 128 + c0;
            float nx[4];
#pragma unroll
            for (int c = 0; c < 4; c++) {
                float a = o[c] - dm;
                nx[c] = fmaxf(g_h[base + c], a);
            }
            float dm2 = warpMax(fmaxf(fmaxf(nx[0], nx[1]), fmaxf(nx[2], nx[3])));
#pragma unroll
            for (int c = 0; c < 4; c++) {
                g_h[base + c] = nx[c];
                g_xn[base + c] = nx[c] - dm2;
            }
        }
    }
}

// ff2: out = trop_mm(g_ff, f2W) (K=256 split 128+128); ff = pnorm(out);
// x = max(x, ff); xn = pnorm(x)
__global__ void __launch_bounds__(512) ff2_kernel(const float* __restrict__ W) {
    __shared__ __align__(16) float As[2][32][18];
    __shared__ __align__(16) float Ws[2][32][132];
    __shared__ float red[16][132];
    const int tid = threadIdx.x;
    const int wg = tid >> 8;
    const int wtid = tid & 255;
    const int m0 = blockIdx.x * 16;
    const int kq = wtid & 7, l = wtid >> 3;
    float acc[2][4];
    float rm[2];
#pragma unroll
    for (int r = 0; r < 2; r++)
#pragma unroll
        for (int c = 0; c < 4; c++) acc[r][c] = NEG;
    const int r0 = (wtid >> 5) * 2, c0 = (wtid & 31) * 4;
    const int kbase = wg * 128;

#pragma unroll
    for (int t = 0; t < 4; t++) {
        int k0 = kbase + t * 32;
        if (wtid < 128) {
            float4 av = *(const float4*)(g_ff + (m0 + l) * 256 + k0 + kq * 4);
            As[wg][kq * 4 + 0][l] = av.x; As[wg][kq * 4 + 1][l] = av.y;
            As[wg][kq * 4 + 2][l] = av.z; As[wg][kq * 4 + 3][l] = av.w;
        }
#pragma unroll
        for (int p = 0; p < 4; p++) {
            int nl = l + p * 32;
            float4 wv = *(const float4*)(W + nl * 256 + k0 + kq * 4);
            Ws[wg][kq * 4 + 0][nl] = wv.x; Ws[wg][kq * 4 + 1][nl] = wv.y;
            Ws[wg][kq * 4 + 2][nl] = wv.z; Ws[wg][kq * 4 + 3][nl] = wv.w;
        }
        __syncthreads();
        innerB<false>(As[wg], Ws[wg], acc, rm, r0, c0);
        __syncthreads();
    }

    if (wg == 1) {
#pragma unroll
        for (int r = 0; r < 2; r++)
#pragma unroll
            for (int c = 0; c < 4; c++) red[r0 + r][c0 + c] = acc[r][c];
    }
    __syncthreads();
    if (wg == 1) return;

#pragma unroll
    for (int r = 0; r < 2; r++) {
        int gm = m0 + r0 + r;
#pragma unroll
        for (int c = 0; c < 4; c++)
            acc[r][c] = fmaxf(acc[r][c], red[r0 + r][c0 + c]);
        float dm = warpMax(fmaxf(fmaxf(acc[r][0], acc[r][1]), fmaxf(acc[r][2], acc[r][3])));
        int base = gm * 128 + c0;
        float nx[4];
#pragma unroll
        for (int c = 0; c < 4; c++)
            nx[c] = fmaxf(g_h[base + c], acc[r][c] - dm);
        float dm2 = warpMax(fmaxf(fmaxf(nx[0], nx[1]), fmaxf(nx[2], nx[3])));
#pragma unroll
        for (int c = 0; c < 4; c++) {
            g_h[base + c] = nx[c];
            g_xn[base + c] = nx[c] - dm2;
        }
    }
}

__global__ void __launch_bounds__(512) pool_kernel() {
    __shared__ float sm[4][128];
    int b = blockIdx.x;
    int d = threadIdx.x & 127;
    int q = threadIdx.x >> 7;
    float m = NEG;
    for (int n = q; n < N_; n += 4)
        m = fmaxf(m, g_h[(b * N_ + n) * D_ + d]);
    sm[q][d] = m;
    __syncthreads();
    if (q == 0) {
        m = fmaxf(fmaxf(sm[0][d], sm[1][d]), fmaxf(sm[2][d], sm[3][d]));
        g_pool[b * D_ + d] = m;
    }
}

__global__ void __launch_bounds__(256) head_kernel(
    const float* __restrict__ hW, const float* __restrict__ ls,
    float* __restrict__ out) {
    __shared__ float sp[128];
    const int b = blockIdx.y;
    const int tid = threadIdx.x;
    if (tid < 128) sp[tid] = g_pool[b * 128 + tid];
    __syncthreads();
    int c = blockIdx.x * 256 + tid;
    if (c < C_) {
        float acc = NEG;
#pragma unroll 8
        for (int d = 0; d < 128; d += 4) {
            float4 w = *(const float4*)(hW + c * 128 + d);
            acc = fmaxf(acc, sp[d + 0] + w.x);
            acc = fmaxf(acc, sp[d + 1] + w.y);
            acc = fmaxf(acc, sp[d + 2] + w.z);
            acc = fmaxf(acc, sp[d + 3] + w.w);
        }
        out[b * C_ + c] = acc * ls[0];
    }
}

extern "C" void kernel_launch(void* const* d_in, const int* in_sizes, int n_in,
                              void* d_out, int out_size) {
    const float* x   = (const float*)d_in[0];
    const float* eW  = (const float*)d_in[1];
    const float* pos = (const float*)d_in[2];
    const float* qW[2]  = {(const float*)d_in[3],  (const float*)d_in[9]};
    const float* kW[2]  = {(const float*)d_in[4],  (const float*)d_in[10]};
    const float* vW[2]  = {(const float*)d_in[5],  (const float*)d_in[11]};
    const float* f1[2]  = {(const float*)d_in[6],  (const float*)d_in[12]};
    const float* f2[2]  = {(const float*)d_in[7],  (const float*)d_in[13]};
    const float* tau[2] = {(const float*)d_in[8],  (const float*)d_in[14]};
    const float* hW = (const float*)d_in[15];
    const float* ls = (const float*)d_in[16];
    float* out = (float*)d_out;

    embed_kernel<<<98, 512>>>(x, eW, pos);                       // g_h, g_xn
    for (int l = 0; l < 2; l++) {
        gemmA_kernel<0><<<dim3(49, 6), 256>>>(qW[l], kW[l], vW[l], nullptr);   // q,k,vt
        gemmA_kernel<1><<<dim3(7, 4, 8), 256>>>(nullptr, nullptr, nullptr, nullptr); // scores
        attnout_kernel<<<dim3(13, 8), 512>>>();                  // fused attn-out + residual + pnorms
        gemmA_kernel<2><<<dim3(49, 4), 256>>>(f1[l], nullptr, nullptr, tau[l]); // ff1 + tau
        ff2_kernel<<<98, 512>>>(f2[l]);                          // ff2 + pnorm + residual + pnorm
    }
    pool_kernel<<<8, 512>>>();
    head_kernel<<<dim3(4, 8), 256>>>(hW, ls, out);
}